// round 14
// baseline (speedup 1.0000x reference)
#include <cuda_runtime.h>

#define DD 128
#define ROWS 8192
#define NTRIU 8256          // DD*(DD+1)/2
#define NQ 2064             // NTRIU / 4
#define OUT_ROW 8384        // DD + NTRIU
#define SH_STRIDE 132       // shifted-copy stride (16B-aligned, padded)

__device__ __forceinline__ float rsqrt_approx(float x) {
    float r;
    asm("rsqrt.approx.f32 %0, %1;" : "=f"(r) : "f"(x));
    return r;
}

__global__ __launch_bounds__(256, 8)
void poly_kernel(const float* __restrict__ x,
                 const float* __restrict__ scales,
                 float* __restrict__ out) {
    // copy r holds xs[m + r] at index m  ->  xs[j..j+3] = aligned float4 in copy (j&3)
    __shared__ float xsh[4 * SH_STRIDE];
    __shared__ float xs2[DD];        // normalized row * scale2
    __shared__ float partial[8];

    const int row = blockIdx.x;
    const int tid = threadIdx.x;

    // ---- load + sum of squares ----
    const float* xr = x + (size_t)row * DD;
    float v = (tid < DD) ? xr[tid] : 0.0f;
    float ss = v * v;
    #pragma unroll
    for (int o = 16; o; o >>= 1)
        ss += __shfl_xor_sync(0xffffffffu, ss, o);
    if ((tid & 31) == 0) partial[tid >> 5] = ss;
    __syncthreads();

    float s = 0.0f;
    #pragma unroll
    for (int w = 0; w < 8; w++) s += partial[w];

    const float inv = 1.0f / fmaxf(sqrtf(s), 1e-12f);
    const float s2 = __ldg(scales + 1);

    float* orow = out + (size_t)row * OUT_ROW;
    const float xn = v * inv;
    if (tid < DD) {
        #pragma unroll
        for (int r = 0; r < 4; r++)
            if (tid >= r) xsh[r * SH_STRIDE + (tid - r)] = xn;
        xs2[tid] = xn * s2;
        orow[tid] = xn;              // degree-1 features (unscaled)
    }
    __syncthreads();

    // ---- degree-2: flat aligned-quad stream, vector LDS gather ----
    // t in [0, NTRIU); segment i covers [base(i), base(i)+DD-i), base(i)=i*(257-i)/2.
    // i = floor((257 - sqrt(257^2-8t))/2 + 3e-4): approx-sqrt with bias, exact for
    // all t (interior slack >= 0.0078, approx err <= ~6e-5, bias covers boundaries).
    float* odeg2 = orow + DD;

    for (int q = tid; q < NQ; q += 256) {
        const int t = 4 * q;
        const float disc = (float)(66049 - 8 * t);       // 257^2 - 8t, exact in fp32
        const float rt = disc * rsqrt_approx(disc);      // ~sqrt(disc)
        int i = (int)((257.0f - rt) * 0.5f + 3e-4f);
        const int base = (i * (257 - i)) >> 1;
        int j = i + (t - base);

        float4 o;
        if (j < 125) {
            // whole quad inside segment i: one aligned vector gather
            const int r = j & 3;
            const float4 xv = *reinterpret_cast<const float4*>(
                xsh + r * SH_STRIDE + (j - r));
            const float a = xs2[i];
            o.x = a * xv.x; o.y = a * xv.y; o.z = a * xv.z; o.w = a * xv.w;
        } else {
            // quad may cross segment boundary(ies): scalar walk with wrap
            float a = xs2[i];
            o.x = a * xsh[j];
            if (++j >= DD) { ++i; j = i; a = xs2[i]; }
            o.y = a * xsh[j];
            if (++j >= DD) { ++i; j = i; a = xs2[i]; }
            o.z = a * xsh[j];
            if (++j >= DD) { ++i; j = i; a = xs2[i]; }
            o.w = a * xsh[j];
        }

        __stcs(reinterpret_cast<float4*>(odeg2 + t), o);
    }
}

extern "C" void kernel_launch(void* const* d_in, const int* in_sizes, int n_in,
                              void* d_out, int out_size) {
    const float* x      = (const float*)d_in[0];
    const float* scales = (const float*)d_in[1];
    float* out          = (float*)d_out;
    poly_kernel<<<ROWS, 256>>>(x, scales, out);
}

// round 15
// speedup vs baseline: 1.0116x; 1.0116x over previous
#include <cuda_runtime.h>

#define DD 128
#define ROWS 8192
#define NTRIU 8256          // DD*(DD+1)/2
#define NQ 2064             // NTRIU / 4
#define OUT_ROW 8384        // DD + NTRIU
#define SH 132              // shifted-replica stride (floats, 16B-aligned)
#define NFIX 384            // fix-list capacity (actual ~190)

// ---- compile-time index tables (depend only on DD) ----
struct Tables {
    unsigned q[NQ];      // per quad: gather byte-off (low 16) | xs2 byte-off (high 16)
    unsigned fix[NFIX];  // displaced elements: t | i<<14 | j<<21 ; 0xFFFFFFFF = empty
};

constexpr Tables make_tables() {
    Tables T{};
    for (int k = 0; k < NFIX; ++k) T.fix[k] = 0xFFFFFFFFu;
    // main quad table: i0/j0 at quad start, aligned replica gather offset
    {
        int i = 0, b = 0, l = DD;
        for (int q = 0; q < NQ; ++q) {
            const int t = 4 * q;
            while (t >= b + l) { b += l; --l; ++i; }
            const int j0 = i + (t - b);
            const int r = j0 & 3;                       // replica select
            const unsigned A = 4u * (unsigned)(r * SH + (j0 - r));  // 16B-aligned
            T.q[q] = A | ((unsigned)(4 * i) << 16);
        }
    }
    // fix list: elements whose true i differs from their quad-start i
    {
        int i = 0, b = 0, l = DD, iq = 0, n = 0;
        for (int t = 0; t < NTRIU; ++t) {
            if ((t & 3) == 0) iq = i;
            if (i != iq) {
                const int j = i + (t - b);
                T.fix[n++] = (unsigned)t | ((unsigned)i << 14) | ((unsigned)j << 21);
            }
            if (t + 1 >= b + l) { b += l; --l; ++i; }
        }
    }
    return T;
}

__device__ constexpr Tables g_tbl = make_tables();

__global__ __launch_bounds__(256, 8)
void poly_kernel(const float* __restrict__ x,
                 const float* __restrict__ scales,
                 float* __restrict__ out) {
    // replica r holds xs[m + r] at xsh[r*SH + m]  ->  xs[j..j+3] is one aligned
    // float4 in replica (j & 3). Padding slots are never selected as final values.
    __shared__ __align__(16) float xsh[4 * SH];
    __shared__ float xs2[DD];        // normalized row * scale2
    __shared__ float partial[8];

    const int row = blockIdx.x;
    const int tid = threadIdx.x;

    // ---- load + sum of squares ----
    const float* xr = x + (size_t)row * DD;
    float v = (tid < DD) ? xr[tid] : 0.0f;
    float ss = v * v;
    #pragma unroll
    for (int o = 16; o; o >>= 1)
        ss += __shfl_xor_sync(0xffffffffu, ss, o);
    if ((tid & 31) == 0) partial[tid >> 5] = ss;
    __syncthreads();

    float s = 0.0f;
    #pragma unroll
    for (int w = 0; w < 8; w++) s += partial[w];

    const float inv = 1.0f / fmaxf(sqrtf(s), 1e-12f);
    const float s2 = __ldg(scales + 1);

    float* orow = out + (size_t)row * OUT_ROW;
    const float xn = v * inv;
    if (tid < DD) {
        #pragma unroll
        for (int r = 0; r < 4; r++)
            if (tid >= r) xsh[r * SH + (tid - r)] = xn;
        xs2[tid] = xn * s2;
        orow[tid] = xn;              // degree-1 features (unscaled)
    }
    __syncthreads();

    float* odeg2 = orow + DD;

    // ---- pass 1: all 2064 quads, branchless, table-driven ----
    // Crossing quads get wrong values at displaced positions; pass 2 overwrites.
    const char* xsh_b = reinterpret_cast<const char*>(xsh);
    const char* xs2_b = reinterpret_cast<const char*>(xs2);
    #pragma unroll 4
    for (int q = tid; q < NQ; q += 256) {
        const unsigned e = __ldg(&g_tbl.q[q]);
        const float4 xv = *reinterpret_cast<const float4*>(xsh_b + (e & 0xFFFFu));
        const float a   = *reinterpret_cast<const float*>(xs2_b + (e >> 16));
        float4 o;
        o.x = a * xv.x; o.y = a * xv.y; o.z = a * xv.z; o.w = a * xv.w;
        __stcs(reinterpret_cast<float4*>(odeg2 + 4 * q), o);
    }

    __syncthreads();   // order pass-1 stores before pass-2 overwrites (block scope)

    // ---- pass 2: patch displaced elements (~190 per row) ----
    for (int c = tid; c < NFIX; c += 256) {
        const unsigned f = __ldg(&g_tbl.fix[c]);
        if (f != 0xFFFFFFFFu) {
            const int t = f & 0x3FFF;
            const int i = (f >> 14) & 0x7F;
            const int j = (f >> 21) & 0x7F;
            odeg2[t] = xs2[i] * xsh[j];     // replica 0 = xs[j]
        }
    }
}

extern "C" void kernel_launch(void* const* d_in, const int* in_sizes, int n_in,
                              void* d_out, int out_size) {
    const float* x      = (const float*)d_in[0];
    const float* scales = (const float*)d_in[1];
    float* out          = (float*)d_out;
    poly_kernel<<<ROWS, 256>>>(x, scales, out);
}